// round 8
// baseline (speedup 1.0000x reference)
#include <cuda_runtime.h>
#include <cuda_bf16.h>

#define N_CLASSES 9
#define N_GROUPS  2
#define N_BINS    (N_CLASSES * N_GROUPS)   // 18
#define THREADS_PER_BLOCK 256
#define CTAS_PER_SM 6
#define NUM_SMS 148

#define DEPTH 4                    // pipeline stages
#define CHUNK_I4 256               // int4 per stage per array (= 1 per thread)
#define CHUNK_BYTES 4096           // bytes per stage per array
#define CHUNK_ELEMS 1024           // elements per stage

// Global scratch (no allocations). Zero-initialized at load; the last block of
// every launch resets everything, so each graph replay sees clean state.
__device__ unsigned int g_counts[N_BINS];
__device__ unsigned int g_ticket;

__device__ __forceinline__ unsigned su32(const void* p) {
    unsigned r;
    asm("{ .reg .u64 t; cvta.to.shared.u64 t, %1; cvt.u32.u64 %0, t; }"
        : "=r"(r) : "l"(p));
    return r;
}

__device__ __forceinline__ void mbar_init(unsigned mb, unsigned count) {
    asm volatile("mbarrier.init.shared::cta.b64 [%0], %1;"
                 :: "r"(mb), "r"(count) : "memory");
}

__device__ __forceinline__ void mbar_expect_tx(unsigned mb, unsigned bytes) {
    asm volatile("mbarrier.arrive.expect_tx.shared::cta.b64 _, [%0], %1;"
                 :: "r"(mb), "r"(bytes) : "memory");
}

__device__ __forceinline__ void bulk_g2s(unsigned dst, const void* src,
                                         unsigned bytes, unsigned mb) {
    asm volatile(
        "cp.async.bulk.shared::cta.global.mbarrier::complete_tx::bytes "
        "[%0], [%1], %2, [%3];"
        :: "r"(dst), "l"(src), "r"(bytes), "r"(mb) : "memory");
}

__device__ __forceinline__ void mbar_wait(unsigned mb, unsigned parity) {
    asm volatile(
        "{\n\t"
        ".reg .pred P;\n"
        "LW_%=:\n\t"
        "mbarrier.try_wait.parity.acquire.cta.shared::cta.b64 P, [%0], %1, 0x989680;\n\t"
        "@P bra LD_%=;\n\t"
        "bra LW_%=;\n"
        "LD_%=:\n\t"
        "}"
        :: "r"(mb), "r"(parity) : "memory");
}

__device__ __forceinline__ void acc_elem(int pred, int attr,
                                         unsigned long long& acc0,
                                         unsigned long long& acc1)
{
    unsigned s = (unsigned)pred * 7u;
    unsigned long long inc = 1ULL << s;
    if (attr) acc1 += inc; else acc0 += inc;   // predicated IADD3/IADD3.X
}

__device__ __forceinline__ void flush_pair(unsigned long long& acc0,
                                           unsigned long long& acc1,
                                           unsigned int* blk)
{
    #pragma unroll
    for (int c = 0; c < N_CLASSES; c++) {
        unsigned f0 = (unsigned)(acc0 >> (7 * c)) & 0x7Fu;
        unsigned f1 = (unsigned)(acc1 >> (7 * c)) & 0x7Fu;
        atomicAdd(&blk[2 * c + 0], f0);   // warp-uniform -> REDUX-aggregated
        atomicAdd(&blk[2 * c + 1], f1);
    }
    acc0 = 0ULL;
    acc1 = 0ULL;
}

__global__ void __launch_bounds__(THREADS_PER_BLOCK, CTAS_PER_SM)
spd_loss_kernel(const int* __restrict__ preds,
                const int* __restrict__ attrs,
                float* __restrict__ out,
                int n, int n4, float n_total)
{
    __shared__ __align__(16) int4 bufp[DEPTH][CHUNK_I4];   // 16 KB
    __shared__ __align__(16) int4 bufa[DEPTH][CHUNK_I4];   // 16 KB
    __shared__ __align__(8) unsigned long long mbar[DEPTH];
    __shared__ unsigned int blk[N_BINS];
    __shared__ unsigned int is_last;

    const int tid = threadIdx.x;
    if (tid < N_BINS) blk[tid] = 0u;
    if (tid == 0) {
        #pragma unroll
        for (int s = 0; s < DEPTH; s++) mbar_init(su32(&mbar[s]), 1);
    }
    __syncthreads();

    unsigned long long a0 = 0ULL, a1 = 0ULL;   // x,y elements
    unsigned long long b0 = 0ULL, b1 = 0ULL;   // z,w elements

    const unsigned full_chunks = (unsigned)(n4 / CHUNK_I4);
    const char* pbytes = (const char*)preds;
    const char* abytes = (const char*)attrs;

    // Remainder [full_chunks*1024, n): block 0, direct LDG (empty for 2^24).
    if (blockIdx.x == 0) {
        for (int k = (int)full_chunks * CHUNK_ELEMS + tid; k < n;
             k += THREADS_PER_BLOCK)
            acc_elem(preds[k], attrs[k], a0, a1);
    }

    // Chunks for this CTA: c = blockIdx.x + k*gridDim.x, k = 0..my-1
    unsigned my = 0;
    if (blockIdx.x < full_chunks)
        my = (full_chunks - 1 - blockIdx.x) / gridDim.x + 1;

    // Prologue: issue up to 3 stages ahead.
    if (tid == 0) {
        unsigned pre = my < (DEPTH - 1) ? my : (DEPTH - 1);
        for (unsigned k = 0; k < pre; k++) {
            unsigned c = blockIdx.x + k * gridDim.x;
            unsigned s = k & (DEPTH - 1);
            unsigned mb = su32(&mbar[s]);
            mbar_expect_tx(mb, 2 * CHUNK_BYTES);
            bulk_g2s(su32(&bufp[s][0]), pbytes + (size_t)c * CHUNK_BYTES,
                     CHUNK_BYTES, mb);
            bulk_g2s(su32(&bufa[s][0]), abytes + (size_t)c * CHUNK_BYTES,
                     CHUNK_BYTES, mb);
        }
    }

    int pending = 0;
    for (unsigned k = 0; k < my; k++) {
        unsigned s  = k & (DEPTH - 1);
        unsigned ph = (k >> 2) & 1;
        mbar_wait(su32(&mbar[s]), ph);

        int4 p = bufp[s][tid];   // LDS.128, conflict-free
        int4 a = bufa[s][tid];
        acc_elem(p.x, a.x, a0, a1);
        acc_elem(p.y, a.y, a0, a1);
        acc_elem(p.z, a.z, b0, b1);
        acc_elem(p.w, a.w, b0, b1);

        // 2 elems/pair/chunk; flush every 40 chunks: 80 < 127 field capacity.
        if (++pending == 40) {
            flush_pair(a0, a1, blk);
            flush_pair(b0, b1, blk);
            pending = 0;
        }

        __syncthreads();   // all consumed stage s -> slot reusable
        if (tid == 0 && k + (DEPTH - 1) < my) {
            unsigned kn = k + (DEPTH - 1);
            unsigned c  = blockIdx.x + kn * gridDim.x;
            unsigned sn = kn & (DEPTH - 1);
            unsigned mb = su32(&mbar[sn]);
            mbar_expect_tx(mb, 2 * CHUNK_BYTES);
            bulk_g2s(su32(&bufp[sn][0]), pbytes + (size_t)c * CHUNK_BYTES,
                     CHUNK_BYTES, mb);
            bulk_g2s(su32(&bufa[sn][0]), abytes + (size_t)c * CHUNK_BYTES,
                     CHUNK_BYTES, mb);
        }
    }

    flush_pair(a0, a1, blk);
    flush_pair(b0, b1, blk);
    __syncthreads();

    // Block totals -> global atomics
    if (tid < N_BINS)
        atomicAdd(&g_counts[tid], blk[tid]);

    // Release + ticket: last block finalizes.
    __syncthreads();
    if (tid == 0) {
        __threadfence();
        unsigned t = atomicAdd(&g_ticket, 1u);
        is_last = (t == gridDim.x - 1) ? 1u : 0u;
    }
    __syncthreads();

    if (is_last && tid == 0) {
        __threadfence();  // acquire side
        float cb[N_BINS];
        #pragma unroll
        for (int c = 0; c < N_BINS; c++)
            cb[c] = (float)atomicAdd(&g_counts[c], 0u);  // coherent read

        float n1 = 0.0f;
        #pragma unroll
        for (int c = 0; c < N_CLASSES; c++) n1 += cb[2 * c + 1];
        float n0 = n_total - n1;

        float s = 0.0f;
        #pragma unroll
        for (int c = 0; c < N_CLASSES; c++) {
            float d = cb[2 * c] / n0 - cb[2 * c + 1] / n1;
            s += d * d;
        }
        out[0] = s;

        // Reset globals for the next graph replay.
        #pragma unroll
        for (int c = 0; c < N_BINS; c++)
            atomicExch(&g_counts[c], 0u);
        __threadfence();
        atomicExch(&g_ticket, 0u);
    }
}

extern "C" void kernel_launch(void* const* d_in, const int* in_sizes, int n_in,
                              void* d_out, int out_size)
{
    const int* preds = (const int*)d_in[0];
    const int* attrs = (const int*)d_in[1];
    float* out = (float*)d_out;
    int n  = in_sizes[0];
    int n4 = n >> 2;

    int blocks = NUM_SMS * CTAS_PER_SM;   // one full wave: 888
    int chunks = n4 / CHUNK_I4;
    if (chunks > 0 && blocks > chunks) blocks = chunks;
    if (blocks < 1) blocks = 1;

    spd_loss_kernel<<<blocks, THREADS_PER_BLOCK>>>(preds, attrs, out, n, n4, (float)n);
}

// round 9
// speedup vs baseline: 1.0714x; 1.0714x over previous
#include <cuda_runtime.h>
#include <cuda_bf16.h>

#define N_CLASSES 9
#define N_GROUPS  2
#define N_BINS    (N_CLASSES * N_GROUPS)   // 18
#define THREADS_PER_BLOCK 256
#define CTAS_PER_SM 8
#define NUM_SMS 148

// Global scratch (no allocations). Zero-initialized at load; the last block of
// every launch resets everything, so each graph replay sees clean state.
__device__ unsigned int g_counts[N_BINS];
__device__ unsigned int g_ticket;

// Packed accumulate: 9 class-fields x 7 bits in a 64-bit register, one
// accumulator per attr value.
__device__ __forceinline__ void acc_elem(int pred, int attr,
                                         unsigned long long& acc0,
                                         unsigned long long& acc1)
{
    unsigned s = (unsigned)pred * 7u;
    unsigned long long inc = 1ULL << s;
    if (attr) acc1 += inc; else acc0 += inc;   // predicated IADD3/IADD3.X
}

__device__ __forceinline__ void flush_pair(unsigned long long& acc0,
                                           unsigned long long& acc1,
                                           unsigned int* blk)
{
    #pragma unroll
    for (int c = 0; c < N_CLASSES; c++) {
        unsigned f0 = (unsigned)(acc0 >> (7 * c)) & 0x7Fu;
        unsigned f1 = (unsigned)(acc1 >> (7 * c)) & 0x7Fu;
        atomicAdd(&blk[2 * c + 0], f0);   // warp-uniform -> REDUX-aggregated
        atomicAdd(&blk[2 * c + 1], f1);
    }
    acc0 = 0ULL;
    acc1 = 0ULL;
}

__global__ void __launch_bounds__(THREADS_PER_BLOCK, CTAS_PER_SM)
spd_loss_kernel(const int* __restrict__ preds,
                const int* __restrict__ attrs,
                float* __restrict__ out,
                int n, int n4, float n_total)
{
    __shared__ unsigned int blk[N_BINS];
    __shared__ unsigned int is_last;

    if (threadIdx.x < N_BINS) blk[threadIdx.x] = 0u;
    __syncthreads();

    // Single accumulator pair (32-reg budget for 8 CTAs/SM residency).
    unsigned long long a0 = 0ULL, a1 = 0ULL;

    const int4* __restrict__ p4 = (const int4*)preds;
    const int4* __restrict__ a4 = (const int4*)attrs;

    const int tid    = blockIdx.x * THREADS_PER_BLOCK + threadIdx.x;
    const int stride = gridDim.x * THREADS_PER_BLOCK;

    // Main loop: 2 int4 pairs per iteration, loads front-batched (4x LDG.128).
    // Safety flush every 15 iterations: 15*8 = 120 < 127 field capacity.
    // (At this size each thread sees ~110 elements, so it fires at most once.)
    int pending = 0;
    int i = tid;
    for (; i + stride < n4; i += 2 * stride) {
        int4 pa = p4[i];
        int4 aa = a4[i];
        int4 pb = p4[i + stride];
        int4 ab = a4[i + stride];

        acc_elem(pa.x, aa.x, a0, a1);
        acc_elem(pa.y, aa.y, a0, a1);
        acc_elem(pa.z, aa.z, a0, a1);
        acc_elem(pa.w, aa.w, a0, a1);
        acc_elem(pb.x, ab.x, a0, a1);
        acc_elem(pb.y, ab.y, a0, a1);
        acc_elem(pb.z, ab.z, a0, a1);
        acc_elem(pb.w, ab.w, a0, a1);

        if (++pending == 15) { flush_pair(a0, a1, blk); pending = 0; }
    }
    for (; i < n4; i += stride) {
        int4 p = p4[i];
        int4 a = a4[i];
        acc_elem(p.x, a.x, a0, a1);
        acc_elem(p.y, a.y, a0, a1);
        acc_elem(p.z, a.z, a0, a1);
        acc_elem(p.w, a.w, a0, a1);
    }

    // Scalar tail (n not multiple of 4) — block 0 only, tiny.
    if (blockIdx.x == 0) {
        for (int k = (n4 << 2) + threadIdx.x; k < n; k += THREADS_PER_BLOCK)
            acc_elem(preds[k], attrs[k], a0, a1);
    }

    flush_pair(a0, a1, blk);
    __syncthreads();

    // Block totals -> global atomics
    if (threadIdx.x < N_BINS)
        atomicAdd(&g_counts[threadIdx.x], blk[threadIdx.x]);

    // Release + ticket: last block finalizes.
    __syncthreads();
    if (threadIdx.x == 0) {
        __threadfence();
        unsigned t = atomicAdd(&g_ticket, 1u);
        is_last = (t == gridDim.x - 1) ? 1u : 0u;
    }
    __syncthreads();

    if (is_last && threadIdx.x == 0) {
        __threadfence();  // acquire side
        float cb[N_BINS];
        #pragma unroll
        for (int c = 0; c < N_BINS; c++)
            cb[c] = (float)atomicAdd(&g_counts[c], 0u);  // coherent read

        float n1 = 0.0f;
        #pragma unroll
        for (int c = 0; c < N_CLASSES; c++) n1 += cb[2 * c + 1];
        float n0 = n_total - n1;

        float s = 0.0f;
        #pragma unroll
        for (int c = 0; c < N_CLASSES; c++) {
            float d = cb[2 * c] / n0 - cb[2 * c + 1] / n1;
            s += d * d;
        }
        out[0] = s;

        // Reset globals for the next graph replay.
        #pragma unroll
        for (int c = 0; c < N_BINS; c++)
            atomicExch(&g_counts[c], 0u);
        __threadfence();
        atomicExch(&g_ticket, 0u);
    }
}

extern "C" void kernel_launch(void* const* d_in, const int* in_sizes, int n_in,
                              void* d_out, int out_size)
{
    const int* preds = (const int*)d_in[0];
    const int* attrs = (const int*)d_in[1];
    float* out = (float*)d_out;
    int n  = in_sizes[0];
    int n4 = n >> 2;

    // One full wave at 8 CTAs/SM (enforced by launch_bounds): 1184 CTAs.
    int blocks = NUM_SMS * CTAS_PER_SM;
    int max_needed = (n4 + THREADS_PER_BLOCK - 1) / THREADS_PER_BLOCK;
    if (blocks > max_needed) blocks = max_needed;
    if (blocks < 1) blocks = 1;

    spd_loss_kernel<<<blocks, THREADS_PER_BLOCK>>>(preds, attrs, out, n, n4, (float)n);
}